// round 3
// baseline (speedup 1.0000x reference)
#include <cuda_runtime.h>

// N=65536 rows, D=512, C=1000.
// 2 rows per warp; ALL 16 float4 loads (8 x + 8 w) explicitly front-batched
// into registers to force MLP_p1=16, then compute. x via __ldcs (streaming,
// keeps the 2MB weight table resident in L2). Fused deterministic final
// reduction via last-block-done counter.

#define N_ROWS   65536
#define D_DIM    512
#define THREADS  256
#define WARPS_PER_BLOCK (THREADS / 32)          // 8
#define ROWS_PER_WARP   2
#define GRID     (N_ROWS / (WARPS_PER_BLOCK * ROWS_PER_WARP))   // 4096

__device__ float g_partial[GRID];
__device__ int   g_count;   // zero-init; last block resets each call

__global__ __launch_bounds__(THREADS) void center_loss_fused(
    const float* __restrict__ x,
    const float* __restrict__ w,
    const int*   __restrict__ t,
    float* __restrict__ out)
{
    const int warp_in_blk = threadIdx.x >> 5;
    const int lane        = threadIdx.x & 31;
    const int gwarp       = blockIdx.x * WARPS_PER_BLOCK + warp_in_blk;
    const int row0        = gwarp * ROWS_PER_WARP;

    const int c0 = t[row0];
    const int c1 = t[row0 + 1];

    const float4* xr0 = reinterpret_cast<const float4*>(x + (size_t)row0 * D_DIM);
    const float4* xr1 = reinterpret_cast<const float4*>(x + (size_t)(row0 + 1) * D_DIM);
    const float4* wr0 = reinterpret_cast<const float4*>(w + (size_t)c0 * D_DIM);
    const float4* wr1 = reinterpret_cast<const float4*>(w + (size_t)c1 * D_DIM);

    // ---- front-batch ALL x loads (DRAM, streaming) ----
    float4 a0[4], a1[4];
    #pragma unroll
    for (int i = 0; i < 4; i++) a0[i] = __ldcs(&xr0[lane + i * 32]);
    #pragma unroll
    for (int i = 0; i < 4; i++) a1[i] = __ldcs(&xr1[lane + i * 32]);

    // ---- then all w loads (L2-resident) ----
    float4 b0[4], b1[4];
    #pragma unroll
    for (int i = 0; i < 4; i++) b0[i] = __ldg(&wr0[lane + i * 32]);
    #pragma unroll
    for (int i = 0; i < 4; i++) b1[i] = __ldg(&wr1[lane + i * 32]);

    float acc0 = 0.0f, acc1 = 0.0f;
    #pragma unroll
    for (int i = 0; i < 4; i++) {
        float d;
        d = a0[i].x - b0[i].x; acc0 = fmaf(d, d, acc0);
        d = a0[i].y - b0[i].y; acc0 = fmaf(d, d, acc0);
        d = a0[i].z - b0[i].z; acc0 = fmaf(d, d, acc0);
        d = a0[i].w - b0[i].w; acc0 = fmaf(d, d, acc0);
        d = a1[i].x - b1[i].x; acc1 = fmaf(d, d, acc1);
        d = a1[i].y - b1[i].y; acc1 = fmaf(d, d, acc1);
        d = a1[i].z - b1[i].z; acc1 = fmaf(d, d, acc1);
        d = a1[i].w - b1[i].w; acc1 = fmaf(d, d, acc1);
    }

    // two interleaved warp butterfly reductions
    #pragma unroll
    for (int o = 16; o > 0; o >>= 1) {
        acc0 += __shfl_xor_sync(0xFFFFFFFFu, acc0, o);
        acc1 += __shfl_xor_sync(0xFFFFFFFFu, acc1, o);
    }

    __shared__ float s[WARPS_PER_BLOCK];
    if (lane == 0)
        s[warp_in_blk] = sqrtf(acc0 + 1e-6f) + sqrtf(acc1 + 1e-6f);
    __syncthreads();

    __shared__ bool is_last;
    if (threadIdx.x == 0) {
        float v = 0.0f;
        #pragma unroll
        for (int i = 0; i < WARPS_PER_BLOCK; i++) v += s[i];
        g_partial[blockIdx.x] = v;
        __threadfence();
        int old = atomicAdd(&g_count, 1);
        is_last = (old == GRID - 1);
    }
    __syncthreads();

    if (is_last) {
        // Deterministic final reduce over 4096 partials with 256 threads.
        float v = 0.0f;
        #pragma unroll
        for (int i = 0; i < GRID / THREADS; i++)
            v += g_partial[threadIdx.x + i * THREADS];
        #pragma unroll
        for (int o = 16; o > 0; o >>= 1)
            v += __shfl_xor_sync(0xFFFFFFFFu, v, o);
        __shared__ float fs[WARPS_PER_BLOCK];
        if (lane == 0) fs[warp_in_blk] = v;
        __syncthreads();
        if (threadIdx.x < 32) {
            float u = (lane < WARPS_PER_BLOCK) ? fs[lane] : 0.0f;
            #pragma unroll
            for (int o = 16; o > 0; o >>= 1)
                u += __shfl_xor_sync(0xFFFFFFFFu, u, o);
            if (threadIdx.x == 0) {
                out[0] = u * (1.0f / (float)N_ROWS);
                g_count = 0;   // reset for next graph replay
            }
        }
    }
}

extern "C" void kernel_launch(void* const* d_in, const int* in_sizes, int n_in,
                              void* d_out, int out_size)
{
    const float* x = (const float*)d_in[0];   // [N, D] fp32
    const float* w = (const float*)d_in[1];   // [C, D] fp32
    const int*   t = (const int*)d_in[2];     // [N] int32
    float* out = (float*)d_out;

    center_loss_fused<<<GRID, THREADS>>>(x, w, t, out);
}